// round 11
// baseline (speedup 1.0000x reference)
#include <cuda_runtime.h>

// Problem constants: B=8192, T=64, D=512
#define BB 8192
#define TT 64
#define DD 512
#define NWPB 4          // warps per block; one warp per batch row

#define FULLM 0xFFFFFFFFu

__device__ __forceinline__ float warp_reduce_sum(float v) {
    #pragma unroll
    for (int off = 16; off > 0; off >>= 1)
        v += __shfl_xor_sync(FULLM, v, off);
    return v;
}

__device__ __forceinline__ float dot4(float4 a, float4 b) {
    return a.x * b.x + a.y * b.y + a.z * b.z + a.w * b.w;
}

__global__ __launch_bounds__(128)
void sdpa_decode_kernel(const float* __restrict__ q,
                        const float* __restrict__ k,
                        const float* __restrict__ v,
                        const int*   __restrict__ pad_mask,
                        float* __restrict__ out,       // [B, D]
                        float* __restrict__ attn_out)  // [B, T]
{
    const int warp = threadIdx.x >> 5;
    const int lane = threadIdx.x & 31;
    const int b    = blockIdx.x * NWPB + warp;   // one warp owns one batch row

    const float INV_TEMP  = 0.04419417382415922f;   // 1/sqrt(512)
    const float MASK_FILL = -1000.0f;

    // ---- q row into registers: 16 floats/lane, layout idx = lane + j*32 ----
    const float4* qrow = reinterpret_cast<const float4*>(q + (size_t)b * DD);
    const float4 q0 = qrow[lane];
    const float4 q1 = qrow[lane + 32];
    const float4 q2 = qrow[lane + 64];
    const float4 q3 = qrow[lane + 96];

    // ---- mask -> 64-bit active set in registers ----
    const int mm0 = pad_mask[(size_t)b * TT + lane];
    const int mm1 = pad_mask[(size_t)b * TT + lane + 32];
    const unsigned am0 = __ballot_sync(FULLM, mm0 == 0);
    const unsigned am1 = __ballot_sync(FULLM, mm1 == 0);
    const unsigned long long act =
        (unsigned long long)am0 | ((unsigned long long)am1 << 32);

    const float4* kbase = reinterpret_cast<const float4*>(k + (size_t)b * TT * DD);
    const float4* vbase = reinterpret_cast<const float4*>(v + (size_t)b * TT * DD);

    float lg0 = MASK_FILL, lg1 = MASK_FILL;  // scaled logits owned by this lane
    float4 acc0 = make_float4(0.f, 0.f, 0.f, 0.f);
    float4 acc1 = acc0, acc2 = acc0, acc3 = acc0;
    float mrun = MASK_FILL;                  // running max (online softmax)
    float srun = 0.0f;                       // running sum

    // ---- SINGLE PASS: per active row pair, load K+V, dot, online update ----
    unsigned long long rem = act;
    while (rem) {
        const int t0 = __ffsll((long long)rem) - 1;
        rem &= rem - 1ull;
        if (rem) {
            const int t1 = __ffsll((long long)rem) - 1;
            rem &= rem - 1ull;
            const float4* ka = kbase + (size_t)t0 * (DD / 4);
            const float4* kb = kbase + (size_t)t1 * (DD / 4);
            float4 a0 = ka[lane], a1 = ka[lane + 32], a2 = ka[lane + 64], a3 = ka[lane + 96];
            float4 c0 = kb[lane], c1 = kb[lane + 32], c2 = kb[lane + 64], c3 = kb[lane + 96];
            // V loads issued BEFORE the reduce chain (independent of it)
            const float4* va = vbase + (size_t)t0 * (DD / 4);
            const float4* vb = vbase + (size_t)t1 * (DD / 4);
            float4 x0 = va[lane], x1 = va[lane + 32], x2 = va[lane + 64], x3 = va[lane + 96];
            float4 y0 = vb[lane], y1 = vb[lane + 32], y2 = vb[lane + 64], y3 = vb[lane + 96];

            float d0 = dot4(a0, q0) + dot4(a1, q1) + dot4(a2, q2) + dot4(a3, q3);
            float d1 = dot4(c0, q0) + dot4(c1, q1) + dot4(c2, q2) + dot4(c3, q3);
            d0 = warp_reduce_sum(d0);        // all lanes get the value
            d1 = warp_reduce_sum(d1);
            const float l0 = d0 * INV_TEMP;
            const float l1 = d1 * INV_TEMP;
            if (lane == (t0 & 31)) { if (t0 < 32) lg0 = l0; else lg1 = l0; }
            if (lane == (t1 & 31)) { if (t1 < 32) lg0 = l1; else lg1 = l1; }

            const float mn   = fmaxf(mrun, fmaxf(l0, l1));
            const float corr = __expf(mrun - mn);
            const float e0   = __expf(l0 - mn);
            const float e1   = __expf(l1 - mn);
            srun = srun * corr + e0 + e1;
            mrun = mn;
            acc0.x = acc0.x * corr + e0 * x0.x + e1 * y0.x;
            acc0.y = acc0.y * corr + e0 * x0.y + e1 * y0.y;
            acc0.z = acc0.z * corr + e0 * x0.z + e1 * y0.z;
            acc0.w = acc0.w * corr + e0 * x0.w + e1 * y0.w;
            acc1.x = acc1.x * corr + e0 * x1.x + e1 * y1.x;
            acc1.y = acc1.y * corr + e0 * x1.y + e1 * y1.y;
            acc1.z = acc1.z * corr + e0 * x1.z + e1 * y1.z;
            acc1.w = acc1.w * corr + e0 * x1.w + e1 * y1.w;
            acc2.x = acc2.x * corr + e0 * x2.x + e1 * y2.x;
            acc2.y = acc2.y * corr + e0 * x2.y + e1 * y2.y;
            acc2.z = acc2.z * corr + e0 * x2.z + e1 * y2.z;
            acc2.w = acc2.w * corr + e0 * x2.w + e1 * y2.w;
            acc3.x = acc3.x * corr + e0 * x3.x + e1 * y3.x;
            acc3.y = acc3.y * corr + e0 * x3.y + e1 * y3.y;
            acc3.z = acc3.z * corr + e0 * x3.z + e1 * y3.z;
            acc3.w = acc3.w * corr + e0 * x3.w + e1 * y3.w;
        } else {
            const float4* ka = kbase + (size_t)t0 * (DD / 4);
            float4 a0 = ka[lane], a1 = ka[lane + 32], a2 = ka[lane + 64], a3 = ka[lane + 96];
            const float4* va = vbase + (size_t)t0 * (DD / 4);
            float4 x0 = va[lane], x1 = va[lane + 32], x2 = va[lane + 64], x3 = va[lane + 96];

            float d0 = dot4(a0, q0) + dot4(a1, q1) + dot4(a2, q2) + dot4(a3, q3);
            d0 = warp_reduce_sum(d0);
            const float l0 = d0 * INV_TEMP;
            if (lane == (t0 & 31)) { if (t0 < 32) lg0 = l0; else lg1 = l0; }

            const float mn   = fmaxf(mrun, l0);
            const float corr = __expf(mrun - mn);
            const float e0   = __expf(l0 - mn);
            srun = srun * corr + e0;
            mrun = mn;
            acc0.x = acc0.x * corr + e0 * x0.x;
            acc0.y = acc0.y * corr + e0 * x0.y;
            acc0.z = acc0.z * corr + e0 * x0.z;
            acc0.w = acc0.w * corr + e0 * x0.w;
            acc1.x = acc1.x * corr + e0 * x1.x;
            acc1.y = acc1.y * corr + e0 * x1.y;
            acc1.z = acc1.z * corr + e0 * x1.z;
            acc1.w = acc1.w * corr + e0 * x1.w;
            acc2.x = acc2.x * corr + e0 * x2.x;
            acc2.y = acc2.y * corr + e0 * x2.y;
            acc2.z = acc2.z * corr + e0 * x2.z;
            acc2.w = acc2.w * corr + e0 * x2.w;
            acc3.x = acc3.x * corr + e0 * x3.x;
            acc3.y = acc3.y * corr + e0 * x3.y;
            acc3.z = acc3.z * corr + e0 * x3.z;
            acc3.w = acc3.w * corr + e0 * x3.w;
        }
    }

    // ---- exact attn output from register-held logits (same math as reference) ----
    float fm = fmaxf(lg0, lg1);
    #pragma unroll
    for (int off = 16; off > 0; off >>= 1)
        fm = fmaxf(fm, __shfl_xor_sync(FULLM, fm, off));
    const float E0 = __expf(lg0 - fm);   // masked lanes underflow to exact 0
    const float E1 = __expf(lg1 - fm);
    const float fs = warp_reduce_sum(E0 + E1);
    const float fi = 1.0f / fs;
    attn_out[(size_t)b * TT + lane]      = E0 * fi;
    attn_out[(size_t)b * TT + lane + 32] = E1 * fi;

    // ---- output ----
    if (act) {
        const float invs = 1.0f / srun;
        acc0.x *= invs; acc0.y *= invs; acc0.z *= invs; acc0.w *= invs;
        acc1.x *= invs; acc1.y *= invs; acc1.z *= invs; acc1.w *= invs;
        acc2.x *= invs; acc2.y *= invs; acc2.z *= invs; acc2.w *= invs;
        acc3.x *= invs; acc3.y *= invs; acc3.z *= invs; acc3.w *= invs;
    } else {
        // all-masked: uniform p = 1/64 over ALL rows (matches reference exactly)
        const float p = 1.0f / 64.0f;
        for (int t = 0; t < TT; t++) {
            const float4* va = vbase + (size_t)t * (DD / 4);
            float4 x0 = va[lane], x1 = va[lane + 32], x2 = va[lane + 64], x3 = va[lane + 96];
            acc0.x += p * x0.x; acc0.y += p * x0.y; acc0.z += p * x0.z; acc0.w += p * x0.w;
            acc1.x += p * x1.x; acc1.y += p * x1.y; acc1.z += p * x1.z; acc1.w += p * x1.w;
            acc2.x += p * x2.x; acc2.y += p * x2.y; acc2.z += p * x2.z; acc2.w += p * x2.w;
            acc3.x += p * x3.x; acc3.y += p * x3.y; acc3.z += p * x3.z; acc3.w += p * x3.w;
        }
    }

    float4* orow = reinterpret_cast<float4*>(out + (size_t)b * DD);
    orow[lane]      = acc0;
    orow[lane + 32] = acc1;
    orow[lane + 64] = acc2;
    orow[lane + 96] = acc3;
}

extern "C" void kernel_launch(void* const* d_in, const int* in_sizes, int n_in,
                              void* d_out, int out_size) {
    const float* q        = (const float*)d_in[0];   // [B, D]
    const float* k        = (const float*)d_in[1];   // [B, T, D]
    const float* v        = (const float*)d_in[2];   // [B, T, D]
    const int*   pad_mask = (const int*)  d_in[3];   // [B, T]

    float* out      = (float*)d_out;                   // [B,1,D]
    float* attn_out = (float*)d_out + (size_t)BB * DD; // [B,1,T]

    sdpa_decode_kernel<<<BB / NWPB, 32 * NWPB>>>(q, k, v, pad_mask, out, attn_out);
}

// round 12
// speedup vs baseline: 1.0452x; 1.0452x over previous
#include <cuda_runtime.h>

// Problem constants: B=8192, T=64, D=512
#define BB 8192
#define TT 64
#define DD 512

__device__ __forceinline__ float warp_reduce_sum(float v) {
    #pragma unroll
    for (int off = 16; off > 0; off >>= 1)
        v += __shfl_xor_sync(0xFFFFFFFFu, v, off);
    return v;
}

__global__ __launch_bounds__(256)
void sdpa_decode_kernel(const float* __restrict__ q,
                        const float* __restrict__ k,
                        const float* __restrict__ v,
                        const int*   __restrict__ pad_mask,
                        float* __restrict__ out,       // [B, D]
                        float* __restrict__ attn_out)  // [B, T]
{
    const int b0   = blockIdx.x * 2;      // this CTA owns rows b0 and b0+1
    const int tid  = threadIdx.x;
    const int warp = tid >> 5;
    const int lane = tid & 31;
    const int half = tid >> 7;            // 0/1: q-load split
    const int htid = tid & 127;

    const float INV_TEMP  = 0.04419417382415922f;   // 1/sqrt(512)
    const float MASK_FILL = -1000.0f;

    __shared__ float4 qs[2][DD / 4];      // q rows
    __shared__ float  s_logit[2][TT];
    __shared__ int    s_mask[2][TT];
    __shared__ float  s_p[2][TT];         // compacted probabilities
    __shared__ int    s_t[2][TT];         // compacted t indices
    __shared__ int    s_n[2];

    // ---- load q rows (half h loads row b0+h) and both masks ----
    qs[half][htid] =
        reinterpret_cast<const float4*>(q + (size_t)(b0 + half) * DD)[htid];
    if (tid < 2 * TT)
        s_mask[tid >> 6][tid & 63] =
            pad_mask[(size_t)(b0 + (tid >> 6)) * TT + (tid & 63)];
    __syncthreads();

    // ---- QK^T for BOTH rows: R7 pair structure, one long dense phase ----
    #pragma unroll
    for (int rr = 0; rr < 2; rr++) {
        const float4* kbase =
            reinterpret_cast<const float4*>(k + (size_t)(b0 + rr) * TT * DD);
        #pragma unroll
        for (int ti = 0; ti < 4; ti++) {
            const int ta = warp + ti * 16;
            const int tb = ta + 8;
            const int ma = s_mask[rr][ta];
            const int mb = s_mask[rr][tb];
            if (!ma && !mb) {
                const float4* ka = kbase + (size_t)ta * (DD / 4);
                const float4* kb = kbase + (size_t)tb * (DD / 4);
                float pa = 0.0f, pb = 0.0f;
                #pragma unroll
                for (int j = 0; j < 4; j++) {
                    const int idx = lane + j * 32;
                    float4 av = ka[idx];
                    float4 bv = kb[idx];
                    float4 qv = qs[rr][idx];
                    pa += av.x * qv.x + av.y * qv.y + av.z * qv.z + av.w * qv.w;
                    pb += bv.x * qv.x + bv.y * qv.y + bv.z * qv.z + bv.w * qv.w;
                }
                pa = warp_reduce_sum(pa);
                pb = warp_reduce_sum(pb);
                if (lane == 0) { s_logit[rr][ta] = pa; s_logit[rr][tb] = pb; }
            } else if (!ma || !mb) {
                const int t = ma ? tb : ta;
                const float4* kr = kbase + (size_t)t * (DD / 4);
                float p = 0.0f;
                #pragma unroll
                for (int j = 0; j < 4; j++) {
                    const int idx = lane + j * 32;
                    float4 kv = kr[idx];
                    float4 qv = qs[rr][idx];
                    p += kv.x * qv.x + kv.y * qv.y + kv.z * qv.z + kv.w * qv.w;
                }
                p = warp_reduce_sum(p);
                if (lane == 0) s_logit[rr][t] = p;
            }
        }
    }
    __syncthreads();

    // ---- masked softmax: warp 0 handles row 0, warp 1 handles row 1 ----
    if (warp < 2) {
        const int rr = warp;
        float v0 = s_mask[rr][lane]      ? MASK_FILL : s_logit[rr][lane]      * INV_TEMP;
        float v1 = s_mask[rr][lane + 32] ? MASK_FILL : s_logit[rr][lane + 32] * INV_TEMP;

        float m = fmaxf(v0, v1);
        #pragma unroll
        for (int off = 16; off > 0; off >>= 1)
            m = fmaxf(m, __shfl_xor_sync(0xFFFFFFFFu, m, off));

        float e0 = __expf(v0 - m);   // underflows to exact 0 for masked (matches ref)
        float e1 = __expf(v1 - m);
        float ssum = warp_reduce_sum(e0 + e1);
        float inv = 1.0f / ssum;
        float p0 = e0 * inv;
        float p1 = e1 * inv;

        attn_out[(size_t)(b0 + rr) * TT + lane]      = p0;
        attn_out[(size_t)(b0 + rr) * TT + lane + 32] = p1;

        // compact nonzero-probability rows (all-masked -> p=1/64, all 64 active)
        bool a0 = (p0 != 0.0f);
        bool a1 = (p1 != 0.0f);
        unsigned bb0 = __ballot_sync(0xFFFFFFFFu, a0);
        unsigned bb1 = __ballot_sync(0xFFFFFFFFu, a1);
        int n0 = __popc(bb0);
        unsigned lt = (1u << lane) - 1u;
        if (a0) { int pos = __popc(bb0 & lt);       s_t[rr][pos] = lane;      s_p[rr][pos] = p0; }
        if (a1) { int pos = n0 + __popc(bb1 & lt);  s_t[rr][pos] = lane + 32; s_p[rr][pos] = p1; }
        if (lane == 0) s_n[rr] = n0 + __popc(bb1);
    }
    __syncthreads();

    // ---- P·V for BOTH rows back-to-back: R7 x8 int-offset loop ----
    #pragma unroll
    for (int rr = 0; rr < 2; rr++) {
        const float2* vbase =
            reinterpret_cast<const float2*>(v + (size_t)(b0 + rr) * TT * DD);
        const float* sp = s_p[rr];
        const int*   st = s_t[rr];
        const int d2 = tid;
        const int n  = s_n[rr];
        float2 acc = make_float2(0.0f, 0.0f);

        int i = 0;
        for (; i + 8 <= n; i += 8) {
            float p0 = sp[i],   p1 = sp[i+1], p2 = sp[i+2], p3 = sp[i+3];
            float p4 = sp[i+4], p5 = sp[i+5], p6 = sp[i+6], p7 = sp[i+7];
            int o0 = st[i]   * (DD / 2) + d2;
            int o1 = st[i+1] * (DD / 2) + d2;
            int o2 = st[i+2] * (DD / 2) + d2;
            int o3 = st[i+3] * (DD / 2) + d2;
            int o4 = st[i+4] * (DD / 2) + d2;
            int o5 = st[i+5] * (DD / 2) + d2;
            int o6 = st[i+6] * (DD / 2) + d2;
            int o7 = st[i+7] * (DD / 2) + d2;
            float2 v0 = vbase[o0], v1 = vbase[o1], v2 = vbase[o2], v3 = vbase[o3];
            float2 v4 = vbase[o4], v5 = vbase[o5], v6 = vbase[o6], v7 = vbase[o7];
            acc.x += p0 * v0.x; acc.y += p0 * v0.y;
            acc.x += p1 * v1.x; acc.y += p1 * v1.y;
            acc.x += p2 * v2.x; acc.y += p2 * v2.y;
            acc.x += p3 * v3.x; acc.y += p3 * v3.y;
            acc.x += p4 * v4.x; acc.y += p4 * v4.y;
            acc.x += p5 * v5.x; acc.y += p5 * v5.y;
            acc.x += p6 * v6.x; acc.y += p6 * v6.y;
            acc.x += p7 * v7.x; acc.y += p7 * v7.y;
        }
        for (; i + 4 <= n; i += 4) {
            float pa = sp[i], pb = sp[i+1], pc = sp[i+2], pd = sp[i+3];
            int oa = st[i]   * (DD / 2) + d2;
            int ob = st[i+1] * (DD / 2) + d2;
            int oc = st[i+2] * (DD / 2) + d2;
            int od = st[i+3] * (DD / 2) + d2;
            float2 va = vbase[oa], vb = vbase[ob], vc = vbase[oc], vd = vbase[od];
            acc.x += pa * va.x; acc.y += pa * va.y;
            acc.x += pb * vb.x; acc.y += pb * vb.y;
            acc.x += pc * vc.x; acc.y += pc * vc.y;
            acc.x += pd * vd.x; acc.y += pd * vd.y;
        }
        for (; i < n; i++) {
            float  p  = sp[i];
            float2 vv = vbase[st[i] * (DD / 2) + d2];
            acc.x += p * vv.x; acc.y += p * vv.y;
        }
        reinterpret_cast<float2*>(out + (size_t)(b0 + rr) * DD)[d2] = acc;
    }
}

extern "C" void kernel_launch(void* const* d_in, const int* in_sizes, int n_in,
                              void* d_out, int out_size) {
    const float* q        = (const float*)d_in[0];   // [B, D]
    const float* k        = (const float*)d_in[1];   // [B, T, D]
    const float* v        = (const float*)d_in[2];   // [B, T, D]
    const int*   pad_mask = (const int*)  d_in[3];   // [B, T]

    float* out      = (float*)d_out;                   // [B,1,D]
    float* attn_out = (float*)d_out + (size_t)BB * DD; // [B,1,T]

    sdpa_decode_kernel<<<BB / 2, 256>>>(q, k, v, pad_mask, out, attn_out);
}

// round 13
// speedup vs baseline: 1.1219x; 1.0734x over previous
#include <cuda_runtime.h>

// Problem constants: B=8192, T=64, D=512
#define BB 8192
#define TT 64
#define DD 512

__device__ __forceinline__ float warp_reduce_sum(float v) {
    #pragma unroll
    for (int off = 16; off > 0; off >>= 1)
        v += __shfl_xor_sync(0xFFFFFFFFu, v, off);
    return v;
}

// streaming (evict-first) float4 / float2 loads for single-use K/V data
__device__ __forceinline__ float4 ldcs4(const float4* p) { return __ldcs(p); }
__device__ __forceinline__ float2 ldcs2(const float2* p) { return __ldcs(p); }

__global__ __launch_bounds__(256)
void sdpa_decode_kernel(const float* __restrict__ q,
                        const float* __restrict__ k,
                        const float* __restrict__ v,
                        const int*   __restrict__ pad_mask,
                        float* __restrict__ out,       // [B, D]
                        float* __restrict__ attn_out)  // [B, T]
{
    const int b    = blockIdx.x;
    const int tid  = threadIdx.x;
    const int warp = tid >> 5;
    const int lane = tid & 31;

    const float INV_TEMP  = 0.04419417382415922f;   // 1/sqrt(512)
    const float MASK_FILL = -1000.0f;

    __shared__ float4 qs[DD / 4];     // q row: 128 float4
    __shared__ float  s_logit[TT];
    __shared__ int    s_mask[TT];
    __shared__ float  s_p[TT];        // compacted probabilities
    __shared__ int    s_t[TT];        // compacted t indices
    __shared__ int    s_n;

    // ---- load q[b] and pad_mask[b] into shared ----
    const float4* q4 = reinterpret_cast<const float4*>(q + (size_t)b * DD);
    if (tid < DD / 4) qs[tid] = q4[tid];
    if (tid < TT)     s_mask[tid] = pad_mask[(size_t)b * TT + tid];
    __syncthreads();

    // ---- QK^T: warp w owns rows {w, w+8, w+16, ..}; process in PAIRS for MLP ----
    const float4* kbase = reinterpret_cast<const float4*>(k + (size_t)b * TT * DD);
    #pragma unroll
    for (int ti = 0; ti < 4; ti++) {
        const int ta = warp + ti * 16;          // first row of pair
        const int tb = ta + 8;                  // second row of pair
        const int ma = s_mask[ta];
        const int mb = s_mask[tb];
        if (!ma && !mb) {
            // both active: 8 independent LDG.128 before the reduces
            const float4* ka = kbase + (size_t)ta * (DD / 4);
            const float4* kb = kbase + (size_t)tb * (DD / 4);
            float pa = 0.0f, pb = 0.0f;
            #pragma unroll
            for (int j = 0; j < 4; j++) {
                const int idx = lane + j * 32;
                float4 av = ldcs4(ka + idx);
                float4 bv = ldcs4(kb + idx);
                float4 qv = qs[idx];
                pa += av.x * qv.x + av.y * qv.y + av.z * qv.z + av.w * qv.w;
                pb += bv.x * qv.x + bv.y * qv.y + bv.z * qv.z + bv.w * qv.w;
            }
            pa = warp_reduce_sum(pa);
            pb = warp_reduce_sum(pb);
            if (lane == 0) { s_logit[ta] = pa; s_logit[tb] = pb; }
        } else if (!ma || !mb) {
            // exactly one active
            const int t = ma ? tb : ta;
            const float4* kr = kbase + (size_t)t * (DD / 4);
            float p = 0.0f;
            #pragma unroll
            for (int j = 0; j < 4; j++) {
                const int idx = lane + j * 32;
                float4 kv = ldcs4(kr + idx);
                float4 qv = qs[idx];
                p += kv.x * qv.x + kv.y * qv.y + kv.z * qv.z + kv.w * qv.w;
            }
            p = warp_reduce_sum(p);
            if (lane == 0) s_logit[t] = p;
        }
    }
    __syncthreads();

    // ---- masked softmax (warp 0, 2 values/lane) + ballot compaction ----
    if (warp == 0) {
        float v0 = s_mask[lane]      ? MASK_FILL : s_logit[lane]      * INV_TEMP;
        float v1 = s_mask[lane + 32] ? MASK_FILL : s_logit[lane + 32] * INV_TEMP;

        float m = fmaxf(v0, v1);
        #pragma unroll
        for (int off = 16; off > 0; off >>= 1)
            m = fmaxf(m, __shfl_xor_sync(0xFFFFFFFFu, m, off));

        float e0 = __expf(v0 - m);   // underflows to exact 0 for masked (matches ref)
        float e1 = __expf(v1 - m);
        float ssum = warp_reduce_sum(e0 + e1);
        float inv = 1.0f / ssum;
        float p0 = e0 * inv;
        float p1 = e1 * inv;

        attn_out[(size_t)b * TT + lane]      = p0;
        attn_out[(size_t)b * TT + lane + 32] = p1;

        // compact nonzero-probability rows (handles all-masked edge case too)
        bool a0 = (p0 != 0.0f);
        bool a1 = (p1 != 0.0f);
        unsigned b0 = __ballot_sync(0xFFFFFFFFu, a0);
        unsigned b1 = __ballot_sync(0xFFFFFFFFu, a1);
        int n0 = __popc(b0);
        unsigned lt = (1u << lane) - 1u;
        if (a0) { int pos = __popc(b0 & lt);       s_t[pos] = lane;      s_p[pos] = p0; }
        if (a1) { int pos = n0 + __popc(b1 & lt);  s_t[pos] = lane + 32; s_p[pos] = p1; }
        if (lane == 0) s_n = n0 + __popc(b1);
    }
    __syncthreads();

    // ---- P·V over ACTIVE rows; 256 threads x float2, unroll x8, int offsets ----
    const float2* vbase = reinterpret_cast<const float2*>(v + (size_t)b * TT * DD);
    const int d2 = tid;                 // float2 index 0..255
    const int n  = s_n;
    float2 acc = make_float2(0.0f, 0.0f);

    int i = 0;
    for (; i + 8 <= n; i += 8) {
        float p0 = s_p[i],   p1 = s_p[i+1], p2 = s_p[i+2], p3 = s_p[i+3];
        float p4 = s_p[i+4], p5 = s_p[i+5], p6 = s_p[i+6], p7 = s_p[i+7];
        int o0 = s_t[i]   * (DD / 2) + d2;
        int o1 = s_t[i+1] * (DD / 2) + d2;
        int o2 = s_t[i+2] * (DD / 2) + d2;
        int o3 = s_t[i+3] * (DD / 2) + d2;
        int o4 = s_t[i+4] * (DD / 2) + d2;
        int o5 = s_t[i+5] * (DD / 2) + d2;
        int o6 = s_t[i+6] * (DD / 2) + d2;
        int o7 = s_t[i+7] * (DD / 2) + d2;
        float2 v0 = ldcs2(vbase + o0), v1 = ldcs2(vbase + o1);
        float2 v2 = ldcs2(vbase + o2), v3 = ldcs2(vbase + o3);
        float2 v4 = ldcs2(vbase + o4), v5 = ldcs2(vbase + o5);
        float2 v6 = ldcs2(vbase + o6), v7 = ldcs2(vbase + o7);
        acc.x += p0 * v0.x; acc.y += p0 * v0.y;
        acc.x += p1 * v1.x; acc.y += p1 * v1.y;
        acc.x += p2 * v2.x; acc.y += p2 * v2.y;
        acc.x += p3 * v3.x; acc.y += p3 * v3.y;
        acc.x += p4 * v4.x; acc.y += p4 * v4.y;
        acc.x += p5 * v5.x; acc.y += p5 * v5.y;
        acc.x += p6 * v6.x; acc.y += p6 * v6.y;
        acc.x += p7 * v7.x; acc.y += p7 * v7.y;
    }
    for (; i + 4 <= n; i += 4) {
        float pa = s_p[i],   pb = s_p[i+1], pc = s_p[i+2], pd = s_p[i+3];
        int oa = s_t[i]   * (DD / 2) + d2;
        int ob = s_t[i+1] * (DD / 2) + d2;
        int oc = s_t[i+2] * (DD / 2) + d2;
        int od = s_t[i+3] * (DD / 2) + d2;
        float2 va = ldcs2(vbase + oa), vb = ldcs2(vbase + ob);
        float2 vc = ldcs2(vbase + oc), vd = ldcs2(vbase + od);
        acc.x += pa * va.x; acc.y += pa * va.y;
        acc.x += pb * vb.x; acc.y += pb * vb.y;
        acc.x += pc * vc.x; acc.y += pc * vc.y;
        acc.x += pd * vd.x; acc.y += pd * vd.y;
    }
    for (; i < n; i++) {
        float  p  = s_p[i];
        float2 vv = ldcs2(vbase + s_t[i] * (DD / 2) + d2);
        acc.x += p * vv.x; acc.y += p * vv.y;
    }
    reinterpret_cast<float2*>(out + (size_t)b * DD)[d2] = acc;
}

extern "C" void kernel_launch(void* const* d_in, const int* in_sizes, int n_in,
                              void* d_out, int out_size) {
    const float* q        = (const float*)d_in[0];   // [B, D]
    const float* k        = (const float*)d_in[1];   // [B, T, D]
    const float* v        = (const float*)d_in[2];   // [B, T, D]
    const int*   pad_mask = (const int*)  d_in[3];   // [B, T]

    float* out      = (float*)d_out;                   // [B,1,D]
    float* attn_out = (float*)d_out + (size_t)BB * DD; // [B,1,T]

    sdpa_decode_kernel<<<BB, 256>>>(q, k, v, pad_mask, out, attn_out);
}